// round 11
// baseline (speedup 1.0000x reference)
#include <cuda_runtime.h>
#include <cuda_fp16.h>
#include <math.h>
#include <cstdint>

#define MTOT 32768   // B*N rows
#define DDIM 1024
#define HDIM 256
#define ADIM 128
#define BB   16
#define NN   2048
#define NEGV (-1e9f)

// ---------------------------------------------------------------------------
// Scratch (__device__ globals; allocation-free rule)
// ---------------------------------------------------------------------------
__device__ __align__(1024) __half g_wh[(size_t)HDIM * DDIM];    // W1 fp16
__device__ __align__(1024) __half g_wah[(size_t)ADIM * HDIM];   // Wa1 fp16
__device__ __align__(1024) float  g_logits[MTOT];

// ---------------------------------------------------------------------------
// Helpers (base sm_100 target: mma.sync / ldmatrix / cp.async only)
// ---------------------------------------------------------------------------
__device__ __forceinline__ uint32_t smem_u32(const void* p) {
    uint32_t r;
    asm("{ .reg .u64 t; cvta.to.shared.u64 t, %1; cvt.u32.u64 %0, t; }"
        : "=r"(r) : "l"(p));
    return r;
}
__device__ __forceinline__ void cpa16(uint32_t dst, const void* src) {
    asm volatile("cp.async.cg.shared.global [%0], [%1], 16;"
                 :: "r"(dst), "l"(src) : "memory");
}
#define CP_COMMIT() asm volatile("cp.async.commit_group;" ::: "memory")
#define CP_WAIT0()  asm volatile("cp.async.wait_group 0;" ::: "memory")

__device__ __forceinline__ void ldsm4(uint32_t* r, uint32_t a) {
    asm volatile("ldmatrix.sync.aligned.m8n8.x4.shared.b16 {%0,%1,%2,%3}, [%4];"
                 : "=r"(r[0]), "=r"(r[1]), "=r"(r[2]), "=r"(r[3]) : "r"(a));
}
__device__ __forceinline__ void mmah(float* c, const uint32_t* a,
                                     uint32_t b0, uint32_t b1) {
    asm volatile(
        "mma.sync.aligned.m16n8k16.row.col.f32.f16.f16.f32 "
        "{%0,%1,%2,%3}, {%4,%5,%6,%7}, {%8,%9}, {%0,%1,%2,%3};"
        : "+f"(c[0]), "+f"(c[1]), "+f"(c[2]), "+f"(c[3])
        : "r"(a[0]), "r"(a[1]), "r"(a[2]), "r"(a[3]), "r"(b0), "r"(b1));
}
__device__ __forceinline__ uint32_t sw64(uint32_t off) {
    return off ^ ((off >> 3) & 0x30);
}
// swizzle for 512-byte rows: bank-rotate 16B granule by row%8
__device__ __forceinline__ uint32_t sw512(uint32_t off) {
    return off ^ ((off >> 5) & 0x70);
}
__device__ __forceinline__ uint32_t pkh2(__half a, __half b) {
    __half2 t = __halves2half2(a, b);   // .x = a = low 16 bits
    return *reinterpret_cast<uint32_t*>(&t);
}
__device__ __forceinline__ float gelu_exact(float y) {
    return 0.5f * y * (1.0f + erff(y * 0.70710678118654752f));
}

// ---------------------------------------------------------------------------
// Weight conversion (f32 -> fp16)
// ---------------------------------------------------------------------------
__global__ __launch_bounds__(256) void convert_w1_kernel(const float* __restrict__ s) {
    size_t i = (size_t)blockIdx.x * 256 + threadIdx.x;
    float4 v = reinterpret_cast<const float4*>(s)[i];
    __half2* dst = reinterpret_cast<__half2*>(g_wh);
    dst[2 * i]     = __floats2half2_rn(v.x, v.y);
    dst[2 * i + 1] = __floats2half2_rn(v.z, v.w);
}
__global__ __launch_bounds__(256) void convert_wa_kernel(const float* __restrict__ s) {
    size_t i = (size_t)blockIdx.x * 256 + threadIdx.x;
    float4 v = reinterpret_cast<const float4*>(s)[i];
    __half2* dst = reinterpret_cast<__half2*>(g_wah);
    dst[2 * i]     = __floats2half2_rn(v.x, v.y);
    dst[2 * i + 1] = __floats2half2_rn(v.z, v.w);
}

// ---------------------------------------------------------------------------
// FUSED kernel: GEMM1 + LN + GELU + instance score + GEMM2 + tanh + logits.
// GEMM1: C = x(32768x1024) @ W1^T: BM=64, BN=256(full), KC=32, 256 thr.
// Inline GEMM2: logits = tanh(h@Wa1^T + ba1).Wa2 + ba2 with h in SMEM.
// Mainloop stage (SW64, 64B rows): A[0,4K) B[4K,20K), double buffered.
// Epilogue: sacc f32 [0,66.5K); h fp16 tile at HOFF (512B rows, sw512).
// Inline GEMM2: Wa1 chunks (8KB) double-buffered at [0,16K); spart at 32K.
// ---------------------------------------------------------------------------
#define ST1   20480
#define HOFF  67584
#define SM1   (HOFF + 32768)   // 100352

__device__ __forceinline__ void cp_w1(uint32_t sb, int c) {
    const int t = threadIdx.x;
    #pragma unroll
    for (int i = 0; i < 4; i++) {
        int a = t + i * 256;           // atom 0..1023: 256 n-rows x 4 atoms
        int row = a >> 2, ac = a & 3;
        uint32_t sw = sw64(row * 64 + ac * 16);
        cpa16(sb + 4096 + sw, g_wh + (size_t)row * DDIM + c * 32 + ac * 8);
    }
}
__device__ __forceinline__ void cp_wa(uint32_t base, int c2) {
    const int t = threadIdx.x;
    #pragma unroll
    for (int i = 0; i < 2; i++) {      // 128 rows x 4 granules = 512
        int a = t + i * 256;
        int row = a >> 2, g = a & 3;
        uint32_t sw = sw64(row * 64 + g * 16);
        cpa16(base + sw, g_wah + (size_t)row * HDIM + c2 * 32 + g * 8);
    }
}

__global__ __launch_bounds__(256, 2) void gemm1_kernel(
        const float* __restrict__ x, const float* __restrict__ b1,
        const float* __restrict__ ln_g, const float* __restrict__ ln_b,
        const float* __restrict__ Wc, const float* __restrict__ bc,
        const float* __restrict__ ba1, const float* __restrict__ Wa2,
        const float* __restrict__ ba2, float* __restrict__ out) {
    extern __shared__ __align__(1024) char smem[];
    const uint32_t sbu = smem_u32(smem);
    const int tid = threadIdx.x, lane = tid & 31, wid = tid >> 5;
    const int bm = blockIdx.x * 64;
    const int arow = tid >> 2, akq = (tid & 3) * 8;   // A-load mapping

    float4 ra, rb;
    {   // prologue: chunk 0
        const float* src = x + (size_t)(bm + arow) * DDIM + akq;
        ra = *(const float4*)src; rb = *(const float4*)(src + 4);
        cp_w1(sbu, 0);
        CP_COMMIT();
    }

    float acc[4][4][4];
    #pragma unroll
    for (int i = 0; i < 4; i++)
        #pragma unroll
        for (int j = 0; j < 4; j++)
            #pragma unroll
            for (int k = 0; k < 4; k++) acc[i][j][k] = 0.0f;

    const int n0 = wid * 32;

    for (int c = 0; c < 32; c++) {
        const uint32_t stg = (uint32_t)(c & 1) * ST1;
        {   // convert+store A for chunk c (regs were prefetched)
            uint32_t off = sw64(arow * 64 + (tid & 3) * 16);
            uint4 hv;
            uint32_t* hp = (uint32_t*)&hv;
            hp[0] = pkh2(__float2half_rn(ra.x), __float2half_rn(ra.y));
            hp[1] = pkh2(__float2half_rn(ra.z), __float2half_rn(ra.w));
            hp[2] = pkh2(__float2half_rn(rb.x), __float2half_rn(rb.y));
            hp[3] = pkh2(__float2half_rn(rb.z), __float2half_rn(rb.w));
            *(uint4*)(smem + stg + off) = hv;
        }
        CP_WAIT0();
        __syncthreads();
        if (c < 31) {   // prefetch chunk c+1
            const float* src = x + (size_t)(bm + arow) * DDIM + (c + 1) * 32 + akq;
            ra = *(const float4*)src; rb = *(const float4*)(src + 4);
            cp_w1(sbu + (uint32_t)((c & 1) ^ 1) * ST1, c + 1);
            CP_COMMIT();
        }
        #pragma unroll
        for (int k16 = 0; k16 < 2; k16++) {
            uint32_t aF[4][4], bF[2][4];
            #pragma unroll
            for (int mt = 0; mt < 4; mt++) {
                uint32_t off = (uint32_t)((mt * 16 + ((lane >> 3) & 1) * 8 + (lane & 7)) * 64
                               + k16 * 32 + ((lane >> 4) & 1) * 16);
                ldsm4(aF[mt], sbu + stg + sw64(off));
            }
            #pragma unroll
            for (int bp = 0; bp < 2; bp++) {
                uint32_t off = (uint32_t)((n0 + bp * 16 + ((lane >> 4) & 1) * 8 + (lane & 7)) * 64
                               + k16 * 32 + ((lane >> 3) & 1) * 16);
                ldsm4(bF[bp], sbu + stg + 4096 + sw64(off));
            }
            #pragma unroll
            for (int mt = 0; mt < 4; mt++)
                #pragma unroll
                for (int nt = 0; nt < 4; nt++)
                    mmah(acc[mt][nt], aF[mt],
                         bF[nt >> 1][(nt & 1) * 2], bF[nt >> 1][(nt & 1) * 2 + 1]);
        }
    }
    __syncthreads();

    // ---- epilogue 1: stage accums (64 x 256, stride 260), per-row LN+GELU,
    //      write h fp16 into SMEM tile at HOFF (512B rows, sw512) ----
    float* sacc = (float*)smem;
    #pragma unroll
    for (int mt = 0; mt < 4; mt++)
        #pragma unroll
        for (int nt = 0; nt < 4; nt++) {
            int row = mt * 16 + (lane >> 2);
            int col = n0 + nt * 8 + (lane & 3) * 2;
            sacc[row * 260 + col]           = acc[mt][nt][0];
            sacc[row * 260 + col + 1]       = acc[mt][nt][1];
            sacc[(row + 8) * 260 + col]     = acc[mt][nt][2];
            sacc[(row + 8) * 260 + col + 1] = acc[mt][nt][3];
        }
    __syncthreads();

    #pragma unroll 1
    for (int it = 0; it < 8; it++) {
        const int row = it * 8 + wid;
        const int grow = bm + row;
        float v[8], s = 0.0f, q = 0.0f;
        #pragma unroll
        for (int i = 0; i < 8; i++) {
            int col = lane + 32 * i;
            v[i] = sacc[row * 260 + col] + __ldg(b1 + col);
            s += v[i]; q += v[i] * v[i];
        }
        #pragma unroll
        for (int o = 16; o; o >>= 1) {
            s += __shfl_xor_sync(0xffffffffu, s, o);
            q += __shfl_xor_sync(0xffffffffu, q, o);
        }
        const float mean = s * (1.0f / 256.0f);
        const float var  = q * (1.0f / 256.0f) - mean * mean;
        const float rstd = rsqrtf(var + 1e-5f);
        float sc = 0.0f;
        #pragma unroll
        for (int i = 0; i < 8; i++) {
            int col = lane + 32 * i;
            float y = (v[i] - mean) * rstd * __ldg(ln_g + col) + __ldg(ln_b + col);
            y = gelu_exact(y);
            sc += y * __ldg(Wc + col);
            *(__half*)(smem + HOFF + sw512((uint32_t)(row * 512 + col * 2))) =
                __float2half_rn(y);
        }
        #pragma unroll
        for (int o = 16; o; o >>= 1) sc += __shfl_xor_sync(0xffffffffu, sc, o);
        if (lane == 0) out[BB + grow] = sc + __ldg(bc);
    }
    __syncthreads();   // h tile complete; sacc region dead from here

    // ---- inline GEMM2: logits = tanh(h @ Wa1^T + ba1) . Wa2 + ba2 ----
    // 8 warps: m0 in {0,32}, n0 32-wide. K=256 in 8 chunks of 32.
    const int m02 = (wid >> 2) * 32, n02 = (wid & 3) * 32;
    cp_wa(sbu, 0);
    CP_COMMIT();

    float ac2[2][4][4];
    #pragma unroll
    for (int i = 0; i < 2; i++)
        #pragma unroll
        for (int j = 0; j < 4; j++)
            #pragma unroll
            for (int k = 0; k < 4; k++) ac2[i][j][k] = 0.0f;

    for (int c2 = 0; c2 < 8; c2++) {
        const uint32_t bstg = (uint32_t)(c2 & 1) * 8192;
        CP_WAIT0();
        __syncthreads();
        if (c2 < 7) {
            cp_wa(sbu + (uint32_t)((c2 & 1) ^ 1) * 8192, c2 + 1);
            CP_COMMIT();
        }
        #pragma unroll
        for (int k16 = 0; k16 < 2; k16++) {
            const int kk = c2 * 2 + k16;
            uint32_t aF[2][4], bF[2][4];
            #pragma unroll
            for (int mt = 0; mt < 2; mt++) {
                uint32_t off = (uint32_t)((m02 + mt * 16 + ((lane >> 3) & 1) * 8 + (lane & 7)) * 512
                               + kk * 32 + ((lane >> 4) & 1) * 16);
                ldsm4(aF[mt], sbu + HOFF + sw512(off));
            }
            #pragma unroll
            for (int bp = 0; bp < 2; bp++) {
                uint32_t off = (uint32_t)((n02 + bp * 16 + ((lane >> 4) & 1) * 8 + (lane & 7)) * 64
                               + k16 * 32 + ((lane >> 3) & 1) * 16);
                ldsm4(bF[bp], sbu + bstg + sw64(off));
            }
            #pragma unroll
            for (int mt = 0; mt < 2; mt++)
                #pragma unroll
                for (int nt = 0; nt < 4; nt++)
                    mmah(ac2[mt][nt], aF[mt],
                         bF[nt >> 1][(nt & 1) * 2], bF[nt >> 1][(nt & 1) * 2 + 1]);
        }
    }
    __syncthreads();

    // ---- epilogue 2: tanh(.+ba1)*Wa2, reduce over n, cross-warp via smem ----
    float* spart = (float*)(smem + 32768);   // [64][5] padded; dead region
    #pragma unroll
    for (int mt = 0; mt < 2; mt++) {
        float r0 = 0.0f, r1 = 0.0f;
        #pragma unroll
        for (int nt = 0; nt < 4; nt++) {
            int col = n02 + nt * 8 + (lane & 3) * 2;
            float w0 = __ldg(Wa2 + col), w1 = __ldg(Wa2 + col + 1);
            float e0 = __ldg(ba1 + col), e1 = __ldg(ba1 + col + 1);
            r0 += tanhf(ac2[mt][nt][0] + e0) * w0 + tanhf(ac2[mt][nt][1] + e1) * w1;
            r1 += tanhf(ac2[mt][nt][2] + e0) * w0 + tanhf(ac2[mt][nt][3] + e1) * w1;
        }
        r0 += __shfl_xor_sync(0xffffffffu, r0, 1);
        r0 += __shfl_xor_sync(0xffffffffu, r0, 2);
        r1 += __shfl_xor_sync(0xffffffffu, r1, 1);
        r1 += __shfl_xor_sync(0xffffffffu, r1, 2);
        if ((lane & 3) == 0) {
            int row = m02 + mt * 16 + (lane >> 2);
            spart[row * 5 + (wid & 3)]       = r0;
            spart[(row + 8) * 5 + (wid & 3)] = r1;
        }
    }
    __syncthreads();
    if (tid < 64) {
        float v = spart[tid * 5 + 0] + spart[tid * 5 + 1]
                + spart[tid * 5 + 2] + spart[tid * 5 + 3] + __ldg(ba2);
        g_logits[bm + tid] = v;
    }
}

// ---------------------------------------------------------------------------
// Finalize: masked softmax pooling + dynamic top-k via 4-round radix-select
// ---------------------------------------------------------------------------
__device__ __forceinline__ float block_sum(float v, float* red) {
    const int lane = threadIdx.x & 31, warp = threadIdx.x >> 5;
    #pragma unroll
    for (int o = 16; o; o >>= 1) v += __shfl_xor_sync(0xffffffffu, v, o);
    __syncthreads();
    if (lane == 0) red[warp] = v;
    __syncthreads();
    if (warp == 0) {
        float t = red[lane];
        #pragma unroll
        for (int o = 16; o; o >>= 1) t += __shfl_xor_sync(0xffffffffu, t, o);
        if (lane == 0) red[0] = t;
    }
    __syncthreads();
    return red[0];
}
__device__ __forceinline__ float block_max(float v, float* red) {
    const int lane = threadIdx.x & 31, warp = threadIdx.x >> 5;
    #pragma unroll
    for (int o = 16; o; o >>= 1)
        v = fmaxf(v, __shfl_xor_sync(0xffffffffu, v, o));
    __syncthreads();
    if (lane == 0) red[warp] = v;
    __syncthreads();
    if (warp == 0) {
        float t = red[lane];
        #pragma unroll
        for (int o = 16; o; o >>= 1)
            t = fmaxf(t, __shfl_xor_sync(0xffffffffu, t, o));
        if (lane == 0) red[0] = t;
    }
    __syncthreads();
    return red[0];
}
__device__ __forceinline__ uint32_t fkey(float f, bool valid) {
    uint32_t u = __float_as_uint(f);
    u = (u & 0x80000000u) ? ~u : (u | 0x80000000u);
    return valid ? u : 0u;
}

__global__ __launch_bounds__(1024) void finalize_kernel(
        const int* __restrict__ lengths, float* __restrict__ out) {
    __shared__ float s_red[32];
    __shared__ uint32_t s_hist[256];
    __shared__ uint32_t s_sel[2];
    const int b = blockIdx.x, tid = threadIdx.x;
    const int T = lengths[b];
    const float* scores = out + BB + (size_t)b * NN;
    const float* logits = g_logits + (size_t)b * NN;

    const float sc0 = scores[tid],        sc1 = scores[tid + 1024];
    const float lg0 = logits[tid],        lg1 = logits[tid + 1024];
    const bool  v0  = tid < T,            v1  = (tid + 1024) < T;
    const float ml0 = v0 ? lg0 : NEGV,    ml1 = v1 ? lg1 : NEGV;

    const float mx  = block_max(fmaxf(ml0, ml1), s_red);
    const float e0  = expf(ml0 - mx), e1 = expf(ml1 - mx);
    const float den = block_sum(e0 + e1, s_red);
    const float num = block_sum((v0 ? e0 * sc0 : 0.0f) +
                                (v1 ? e1 * sc1 : 0.0f), s_red);
    const float attn = num / den;

    // ---- radix-select k-th largest (exact, with tie handling) ----
    const uint32_t k0 = fkey(sc0, v0), k1 = fkey(sc1, v1);
    int kk = T / 10;
    if (kk < 1) kk = 1;
    uint32_t prefix = 0, rem = (uint32_t)kk;

    #pragma unroll 1
    for (int shift = 24; shift >= 0; shift -= 8) {
        if (tid < 256) s_hist[tid] = 0;
        __syncthreads();
        const uint32_t msk = (shift == 24) ? 0u : (0xFFFFFFFFu << (shift + 8));
        if ((k0 & msk) == prefix) atomicAdd(&s_hist[(k0 >> shift) & 255], 1u);
        if ((k1 & msk) == prefix) atomicAdd(&s_hist[(k1 >> shift) & 255], 1u);
        __syncthreads();
        if (tid < 32) {
            const int hi = 255 - tid * 8;
            uint32_t cnt[8], csum = 0;
            #pragma unroll
            for (int i = 0; i < 8; i++) { cnt[i] = s_hist[hi - i]; csum += cnt[i]; }
            uint32_t run = csum;
            #pragma unroll
            for (int o = 1; o < 32; o <<= 1) {
                uint32_t t = __shfl_up_sync(0xffffffffu, run, o);
                if (tid >= o) run += t;
            }
            const uint32_t excl = run - csum;
            if (excl < rem && rem <= excl + csum) {
                uint32_t r = rem - excl, c2 = 0;
                #pragma unroll
                for (int i = 0; i < 8; i++) {
                    if (c2 + cnt[i] >= r) { s_sel[0] = (uint32_t)(hi - i);
                                            s_sel[1] = r - c2; break; }
                    c2 += cnt[i];
                }
            }
        }
        __syncthreads();
        prefix |= s_sel[0] << shift;
        rem = s_sel[1];
        __syncthreads();
    }

    const uint32_t tkey = prefix;
    const float thr = (tkey & 0x80000000u)
                    ? __uint_as_float(tkey ^ 0x80000000u)
                    : __uint_as_float(~tkey);
    const float sg = (k0 > tkey ? sc0 : 0.0f) + (k1 > tkey ? sc1 : 0.0f);
    const float sum_gt = block_sum(sg, s_red);
    const float tsum = sum_gt + (float)rem * thr;

    if (tid == 0)
        out[b] = (T > 0) ? 0.5f * attn + 0.5f * (tsum / (float)kk) : 0.0f;
}

// ---------------------------------------------------------------------------
extern "C" void kernel_launch(void* const* d_in, const int* in_sizes, int n_in,
                              void* d_out, int out_size) {
    const float* x    = (const float*)d_in[0];
    const int*   lens = (const int*)  d_in[1];
    const float* W1   = (const float*)d_in[2];
    const float* b1   = (const float*)d_in[3];
    const float* ln_g = (const float*)d_in[4];
    const float* ln_b = (const float*)d_in[5];
    const float* Wa1  = (const float*)d_in[6];
    const float* ba1  = (const float*)d_in[7];
    const float* Wa2  = (const float*)d_in[8];
    const float* ba2  = (const float*)d_in[9];
    const float* Wc   = (const float*)d_in[10];
    const float* bc   = (const float*)d_in[11];
    float* out = (float*)d_out;

    // idempotent, executes immediately (not stream-captured)
    cudaFuncSetAttribute(gemm1_kernel,
                         cudaFuncAttributeMaxDynamicSharedMemorySize, SM1);

    convert_w1_kernel<<<HDIM * DDIM / 1024, 256>>>(W1);
    convert_wa_kernel<<<ADIM * HDIM / 1024, 256>>>(Wa1);
    gemm1_kernel<<<MTOT / 64, 256, SM1>>>(x, b1, ln_g, ln_b, Wc, bc,
                                          ba1, Wa2, ba2, out);
    finalize_kernel<<<BB, 1024>>>(lens, out);
}

// round 12
// speedup vs baseline: 1.3025x; 1.3025x over previous
#include <cuda_runtime.h>
#include <cuda_fp16.h>
#include <math.h>
#include <cstdint>

#define MTOT 32768   // B*N rows
#define DDIM 1024
#define HDIM 256
#define ADIM 128
#define BB   16
#define NN   2048
#define NEGV (-1e9f)

// ---------------------------------------------------------------------------
// Scratch (__device__ globals; allocation-free rule)
// ---------------------------------------------------------------------------
__device__ __align__(1024) __half g_wh[(size_t)HDIM * DDIM];    // W1 fp16
__device__ __align__(1024) __half g_wah[(size_t)ADIM * HDIM];   // Wa1 fp16
__device__ __align__(1024) __half g_hf[(size_t)MTOT * HDIM];    // h fp16
__device__ __align__(1024) float  g_logits[MTOT];

// ---------------------------------------------------------------------------
// Helpers (base sm_100 target: mma.sync / ldmatrix / cp.async only)
// ---------------------------------------------------------------------------
__device__ __forceinline__ uint32_t smem_u32(const void* p) {
    uint32_t r;
    asm("{ .reg .u64 t; cvta.to.shared.u64 t, %1; cvt.u32.u64 %0, t; }"
        : "=r"(r) : "l"(p));
    return r;
}
__device__ __forceinline__ void cpa16(uint32_t dst, const void* src) {
    asm volatile("cp.async.cg.shared.global [%0], [%1], 16;"
                 :: "r"(dst), "l"(src) : "memory");
}
#define CP_COMMIT() asm volatile("cp.async.commit_group;" ::: "memory")
#define CP_WAIT0()  asm volatile("cp.async.wait_group 0;" ::: "memory")
#define CP_WAIT1()  asm volatile("cp.async.wait_group 1;" ::: "memory")

__device__ __forceinline__ void ldsm4(uint32_t* r, uint32_t a) {
    asm volatile("ldmatrix.sync.aligned.m8n8.x4.shared.b16 {%0,%1,%2,%3}, [%4];"
                 : "=r"(r[0]), "=r"(r[1]), "=r"(r[2]), "=r"(r[3]) : "r"(a));
}
__device__ __forceinline__ void mmah(float* c, const uint32_t* a,
                                     uint32_t b0, uint32_t b1) {
    asm volatile(
        "mma.sync.aligned.m16n8k16.row.col.f32.f16.f16.f32 "
        "{%0,%1,%2,%3}, {%4,%5,%6,%7}, {%8,%9}, {%0,%1,%2,%3};"
        : "+f"(c[0]), "+f"(c[1]), "+f"(c[2]), "+f"(c[3])
        : "r"(a[0]), "r"(a[1]), "r"(a[2]), "r"(a[3]), "r"(b0), "r"(b1));
}
__device__ __forceinline__ uint32_t sw64(uint32_t off) {
    return off ^ ((off >> 3) & 0x30);
}
__device__ __forceinline__ uint32_t pkh2(__half a, __half b) {
    __half2 t = __halves2half2(a, b);   // .x = a = low 16 bits
    return *reinterpret_cast<uint32_t*>(&t);
}
__device__ __forceinline__ float gelu_exact(float y) {
    return 0.5f * y * (1.0f + erff(y * 0.70710678118654752f));
}

// ---------------------------------------------------------------------------
// Weight conversion (f32 -> fp16)
// ---------------------------------------------------------------------------
__global__ __launch_bounds__(256) void convert_w1_kernel(const float* __restrict__ s) {
    size_t i = (size_t)blockIdx.x * 256 + threadIdx.x;
    float4 v = reinterpret_cast<const float4*>(s)[i];
    __half2* dst = reinterpret_cast<__half2*>(g_wh);
    dst[2 * i]     = __floats2half2_rn(v.x, v.y);
    dst[2 * i + 1] = __floats2half2_rn(v.z, v.w);
}
__global__ __launch_bounds__(256) void convert_wa_kernel(const float* __restrict__ s) {
    size_t i = (size_t)blockIdx.x * 256 + threadIdx.x;
    float4 v = reinterpret_cast<const float4*>(s)[i];
    __half2* dst = reinterpret_cast<__half2*>(g_wah);
    dst[2 * i]     = __floats2half2_rn(v.x, v.y);
    dst[2 * i + 1] = __floats2half2_rn(v.z, v.w);
}

// ---------------------------------------------------------------------------
// GEMM1 + LN + GELU + instance score, fused.
// C = x(32768x1024) @ W1^T(1024x256): BM=64, BN=256(full), KC=32, 256 thr.
// Single-pass fp16; 3-stage W pipeline (wait_group 1), 2-stage A.
// SMEM: W stages 3x16K at [0,48K); A stages 2x4K at [48K,56K);
//       epilogue sacc f32 64x260 aliased from 0 (66.5K) -> SM1 = 66560.
// ---------------------------------------------------------------------------
#define W1OFF 0
#define A1OFF 49152
#define SM1   66560

__device__ __forceinline__ void cp_w1(uint32_t stage_base, int c) {
    const int t = threadIdx.x;
    #pragma unroll
    for (int i = 0; i < 4; i++) {
        int a = t + i * 256;           // atom 0..1023: 256 n-rows x 4 atoms
        int row = a >> 2, ac = a & 3;
        uint32_t sw = sw64(row * 64 + ac * 16);
        cpa16(stage_base + sw, g_wh + (size_t)row * DDIM + c * 32 + ac * 8);
    }
}

__global__ __launch_bounds__(256, 2) void gemm1_kernel(
        const float* __restrict__ x, const float* __restrict__ b1,
        const float* __restrict__ ln_g, const float* __restrict__ ln_b,
        const float* __restrict__ Wc, const float* __restrict__ bc,
        float* __restrict__ out) {
    extern __shared__ __align__(1024) char smem[];
    const uint32_t sbu = smem_u32(smem);
    const int tid = threadIdx.x, lane = tid & 31, wid = tid >> 5;
    const int bm = blockIdx.x * 64;
    const int arow = tid >> 2, akq = (tid & 3) * 8;   // A-load mapping

    float4 ra, rb;
    {   // prologue: A regs for chunk 0; W chunks 0 and 1 in flight
        const float* src = x + (size_t)(bm + arow) * DDIM + akq;
        ra = *(const float4*)src; rb = *(const float4*)(src + 4);
        cp_w1(sbu + W1OFF, 0);
        CP_COMMIT();
        cp_w1(sbu + W1OFF + 16384, 1);
        CP_COMMIT();
    }

    float acc[4][4][4];
    #pragma unroll
    for (int i = 0; i < 4; i++)
        #pragma unroll
        for (int j = 0; j < 4; j++)
            #pragma unroll
            for (int k = 0; k < 4; k++) acc[i][j][k] = 0.0f;

    const int n0 = wid * 32;

    for (int c = 0; c < 32; c++) {
        const uint32_t astg = A1OFF + (uint32_t)(c & 1) * 4096;
        const uint32_t wstg = W1OFF + (uint32_t)(c % 3) * 16384;
        {   // convert+store A for chunk c (regs were prefetched)
            uint32_t off = sw64(arow * 64 + (tid & 3) * 16);
            uint4 hv;
            uint32_t* hp = (uint32_t*)&hv;
            hp[0] = pkh2(__float2half_rn(ra.x), __float2half_rn(ra.y));
            hp[1] = pkh2(__float2half_rn(ra.z), __float2half_rn(ra.w));
            hp[2] = pkh2(__float2half_rn(rb.x), __float2half_rn(rb.y));
            hp[3] = pkh2(__float2half_rn(rb.z), __float2half_rn(rb.w));
            *(uint4*)(smem + astg + off) = hv;
        }
        if (c < 31) { CP_WAIT1(); } else { CP_WAIT0(); }
        __syncthreads();
        if (c < 31) {   // prefetch A regs for chunk c+1
            const float* src = x + (size_t)(bm + arow) * DDIM + (c + 1) * 32 + akq;
            ra = *(const float4*)src; rb = *(const float4*)(src + 4);
        }
        if (c < 30) {   // keep two W chunks in flight
            cp_w1(sbu + W1OFF + (uint32_t)((c + 2) % 3) * 16384, c + 2);
            CP_COMMIT();
        }
        #pragma unroll
        for (int k16 = 0; k16 < 2; k16++) {
            uint32_t aF[4][4], bF[2][4];
            #pragma unroll
            for (int mt = 0; mt < 4; mt++) {
                uint32_t off = (uint32_t)((mt * 16 + ((lane >> 3) & 1) * 8 + (lane & 7)) * 64
                               + k16 * 32 + ((lane >> 4) & 1) * 16);
                ldsm4(aF[mt], sbu + astg + sw64(off));
            }
            #pragma unroll
            for (int bp = 0; bp < 2; bp++) {
                uint32_t off = (uint32_t)((n0 + bp * 16 + ((lane >> 4) & 1) * 8 + (lane & 7)) * 64
                               + k16 * 32 + ((lane >> 3) & 1) * 16);
                ldsm4(bF[bp], sbu + wstg + sw64(off));
            }
            #pragma unroll
            for (int mt = 0; mt < 4; mt++)
                #pragma unroll
                for (int nt = 0; nt < 4; nt++)
                    mmah(acc[mt][nt], aF[mt],
                         bF[nt >> 1][(nt & 1) * 2], bF[nt >> 1][(nt & 1) * 2 + 1]);
        }
    }
    __syncthreads();

    // ---- epilogue: stage accums (64 x 256, stride 260), per-row LN+GELU ----
    float* sacc = (float*)smem;
    #pragma unroll
    for (int mt = 0; mt < 4; mt++)
        #pragma unroll
        for (int nt = 0; nt < 4; nt++) {
            int row = mt * 16 + (lane >> 2);
            int col = n0 + nt * 8 + (lane & 3) * 2;
            sacc[row * 260 + col]           = acc[mt][nt][0];
            sacc[row * 260 + col + 1]       = acc[mt][nt][1];
            sacc[(row + 8) * 260 + col]     = acc[mt][nt][2];
            sacc[(row + 8) * 260 + col + 1] = acc[mt][nt][3];
        }
    __syncthreads();

    #pragma unroll 1
    for (int it = 0; it < 8; it++) {
        const int row = it * 8 + wid;
        const int grow = bm + row;
        float v[8], s = 0.0f, q = 0.0f;
        #pragma unroll
        for (int i = 0; i < 8; i++) {
            int col = lane + 32 * i;
            v[i] = sacc[row * 260 + col] + __ldg(b1 + col);
            s += v[i]; q += v[i] * v[i];
        }
        #pragma unroll
        for (int o = 16; o; o >>= 1) {
            s += __shfl_xor_sync(0xffffffffu, s, o);
            q += __shfl_xor_sync(0xffffffffu, q, o);
        }
        const float mean = s * (1.0f / 256.0f);
        const float var  = q * (1.0f / 256.0f) - mean * mean;
        const float rstd = rsqrtf(var + 1e-5f);
        float sc = 0.0f;
        #pragma unroll
        for (int i = 0; i < 8; i++) {
            int col = lane + 32 * i;
            float y = (v[i] - mean) * rstd * __ldg(ln_g + col) + __ldg(ln_b + col);
            y = gelu_exact(y);
            sc += y * __ldg(Wc + col);
            g_hf[(size_t)grow * HDIM + col] = __float2half_rn(y);
        }
        #pragma unroll
        for (int o = 16; o; o >>= 1) sc += __shfl_xor_sync(0xffffffffu, sc, o);
        if (lane == 0) out[BB + grow] = sc + __ldg(bc);
    }
}

// ---------------------------------------------------------------------------
// GEMM2 + tanh + Wa2 reduce, fused.  logits = tanh(h@Wa1^T + ba1).Wa2 + ba2
// M=32768, N=128(full), K=256: BM=64, BN=128, KC=32, 256 thr (2m x 4n warps)
// 3-stage pipeline: stage s at s*12288: A[+0,4K) B[+4K,12K). SM2 = 36864.
// ---------------------------------------------------------------------------
#define SM2 36864

__device__ __forceinline__ void cp_h2(uint32_t stage_base, int c, int bm) {
    const int t = threadIdx.x;
    {   // A: 64 rows x 4 atoms = 256
        int row = t >> 2, ac = t & 3;
        uint32_t sw = sw64(row * 64 + ac * 16);
        cpa16(stage_base + sw, g_hf + (size_t)(bm + row) * HDIM + c * 32 + ac * 8);
    }
    #pragma unroll
    for (int i = 0; i < 2; i++) {      // B: 128 rows x 4 atoms = 512
        int a = t + i * 256;
        int row = a >> 2, ac = a & 3;
        uint32_t sw = sw64(row * 64 + ac * 16);
        cpa16(stage_base + 4096 + sw, g_wah + (size_t)row * HDIM + c * 32 + ac * 8);
    }
}

__global__ __launch_bounds__(256, 2) void gemm2_kernel(
        const float* __restrict__ ba1, const float* __restrict__ Wa2,
        const float* __restrict__ ba2) {
    extern __shared__ __align__(1024) char smem[];
    const uint32_t sbu = smem_u32(smem);
    const int tid = threadIdx.x, lane = tid & 31, wid = tid >> 5;
    const int bm = blockIdx.x * 64;
    const int m0 = (wid >> 2) * 32, n0 = (wid & 3) * 32;

    cp_h2(sbu, 0, bm);
    CP_COMMIT();
    cp_h2(sbu + 12288, 1, bm);
    CP_COMMIT();

    float acc[2][4][4];
    #pragma unroll
    for (int i = 0; i < 2; i++)
        #pragma unroll
        for (int j = 0; j < 4; j++)
            #pragma unroll
            for (int k = 0; k < 4; k++) acc[i][j][k] = 0.0f;

    for (int c = 0; c < 8; c++) {
        const uint32_t stg = (uint32_t)(c % 3) * 12288;
        if (c < 7) { CP_WAIT1(); } else { CP_WAIT0(); }
        __syncthreads();
        if (c < 6) {
            cp_h2(sbu + (uint32_t)((c + 2) % 3) * 12288, c + 2, bm);
            CP_COMMIT();
        }
        #pragma unroll
        for (int k16 = 0; k16 < 2; k16++) {
            uint32_t aF[2][4], bF[2][4];
            #pragma unroll
            for (int mt = 0; mt < 2; mt++) {
                uint32_t off = (uint32_t)((m0 + mt * 16 + ((lane >> 3) & 1) * 8 + (lane & 7)) * 64
                               + k16 * 32 + ((lane >> 4) & 1) * 16);
                ldsm4(aF[mt], sbu + stg + sw64(off));
            }
            #pragma unroll
            for (int bp = 0; bp < 2; bp++) {
                uint32_t off = (uint32_t)((n0 + bp * 16 + ((lane >> 4) & 1) * 8 + (lane & 7)) * 64
                               + k16 * 32 + ((lane >> 3) & 1) * 16);
                ldsm4(bF[bp], sbu + stg + 4096 + sw64(off));
            }
            #pragma unroll
            for (int mt = 0; mt < 2; mt++)
                #pragma unroll
                for (int nt = 0; nt < 4; nt++)
                    mmah(acc[mt][nt], aF[mt],
                         bF[nt >> 1][(nt & 1) * 2], bF[nt >> 1][(nt & 1) * 2 + 1]);
        }
    }
    __syncthreads();

    // ---- epilogue: tanh(.+ba1)*Wa2, reduce over n, cross-warp via smem ----
    float* spart = (float*)smem;   // [64][5] padded
    #pragma unroll
    for (int mt = 0; mt < 2; mt++) {
        float r0 = 0.0f, r1 = 0.0f;
        #pragma unroll
        for (int nt = 0; nt < 4; nt++) {
            int col = n0 + nt * 8 + (lane & 3) * 2;
            float w0 = __ldg(Wa2 + col), w1 = __ldg(Wa2 + col + 1);
            float e0 = __ldg(ba1 + col), e1 = __ldg(ba1 + col + 1);
            r0 += tanhf(acc[mt][nt][0] + e0) * w0 + tanhf(acc[mt][nt][1] + e1) * w1;
            r1 += tanhf(acc[mt][nt][2] + e0) * w0 + tanhf(acc[mt][nt][3] + e1) * w1;
        }
        r0 += __shfl_xor_sync(0xffffffffu, r0, 1);
        r0 += __shfl_xor_sync(0xffffffffu, r0, 2);
        r1 += __shfl_xor_sync(0xffffffffu, r1, 1);
        r1 += __shfl_xor_sync(0xffffffffu, r1, 2);
        if ((lane & 3) == 0) {
            int row = m0 + mt * 16 + (lane >> 2);
            spart[row * 5 + (wid & 3)]       = r0;
            spart[(row + 8) * 5 + (wid & 3)] = r1;
        }
    }
    __syncthreads();
    if (tid < 64) {
        float v = spart[tid * 5 + 0] + spart[tid * 5 + 1]
                + spart[tid * 5 + 2] + spart[tid * 5 + 3] + __ldg(ba2);
        g_logits[bm + tid] = v;
    }
}

// ---------------------------------------------------------------------------
// Finalize: masked softmax pooling + dynamic top-k via 4-round radix-select
// ---------------------------------------------------------------------------
__device__ __forceinline__ float block_sum(float v, float* red) {
    const int lane = threadIdx.x & 31, warp = threadIdx.x >> 5;
    #pragma unroll
    for (int o = 16; o; o >>= 1) v += __shfl_xor_sync(0xffffffffu, v, o);
    __syncthreads();
    if (lane == 0) red[warp] = v;
    __syncthreads();
    if (warp == 0) {
        float t = red[lane];
        #pragma unroll
        for (int o = 16; o; o >>= 1) t += __shfl_xor_sync(0xffffffffu, t, o);
        if (lane == 0) red[0] = t;
    }
    __syncthreads();
    return red[0];
}
__device__ __forceinline__ float block_max(float v, float* red) {
    const int lane = threadIdx.x & 31, warp = threadIdx.x >> 5;
    #pragma unroll
    for (int o = 16; o; o >>= 1)
        v = fmaxf(v, __shfl_xor_sync(0xffffffffu, v, o));
    __syncthreads();
    if (lane == 0) red[warp] = v;
    __syncthreads();
    if (warp == 0) {
        float t = red[lane];
        #pragma unroll
        for (int o = 16; o; o >>= 1)
            t = fmaxf(t, __shfl_xor_sync(0xffffffffu, t, o));
        if (lane == 0) red[0] = t;
    }
    __syncthreads();
    return red[0];
}
__device__ __forceinline__ uint32_t fkey(float f, bool valid) {
    uint32_t u = __float_as_uint(f);
    u = (u & 0x80000000u) ? ~u : (u | 0x80000000u);
    return valid ? u : 0u;
}

__global__ __launch_bounds__(1024) void finalize_kernel(
        const int* __restrict__ lengths, float* __restrict__ out) {
    __shared__ float s_red[32];
    __shared__ uint32_t s_hist[256];
    __shared__ uint32_t s_sel[2];
    const int b = blockIdx.x, tid = threadIdx.x;
    const int T = lengths[b];
    const float* scores = out + BB + (size_t)b * NN;
    const float* logits = g_logits + (size_t)b * NN;

    const float sc0 = scores[tid],        sc1 = scores[tid + 1024];
    const float lg0 = logits[tid],        lg1 = logits[tid + 1024];
    const bool  v0  = tid < T,            v1  = (tid + 1024) < T;
    const float ml0 = v0 ? lg0 : NEGV,    ml1 = v1 ? lg1 : NEGV;

    const float mx  = block_max(fmaxf(ml0, ml1), s_red);
    const float e0  = expf(ml0 - mx), e1 = expf(ml1 - mx);
    const float den = block_sum(e0 + e1, s_red);
    const float num = block_sum((v0 ? e0 * sc0 : 0.0f) +
                                (v1 ? e1 * sc1 : 0.0f), s_red);
    const float attn = num / den;

    // ---- radix-select k-th largest (exact, with tie handling) ----
    const uint32_t k0 = fkey(sc0, v0), k1 = fkey(sc1, v1);
    int kk = T / 10;
    if (kk < 1) kk = 1;
    uint32_t prefix = 0, rem = (uint32_t)kk;

    #pragma unroll 1
    for (int shift = 24; shift >= 0; shift -= 8) {
        if (tid < 256) s_hist[tid] = 0;
        __syncthreads();
        const uint32_t msk = (shift == 24) ? 0u : (0xFFFFFFFFu << (shift + 8));
        if ((k0 & msk) == prefix) atomicAdd(&s_hist[(k0 >> shift) & 255], 1u);
        if ((k1 & msk) == prefix) atomicAdd(&s_hist[(k1 >> shift) & 255], 1u);
        __syncthreads();
        if (tid < 32) {
            const int hi = 255 - tid * 8;
            uint32_t cnt[8], csum = 0;
            #pragma unroll
            for (int i = 0; i < 8; i++) { cnt[i] = s_hist[hi - i]; csum += cnt[i]; }
            uint32_t run = csum;
            #pragma unroll
            for (int o = 1; o < 32; o <<= 1) {
                uint32_t t = __shfl_up_sync(0xffffffffu, run, o);
                if (tid >= o) run += t;
            }
            const uint32_t excl = run - csum;
            if (excl < rem && rem <= excl + csum) {
                uint32_t r = rem - excl, c2 = 0;
                #pragma unroll
                for (int i = 0; i < 8; i++) {
                    if (c2 + cnt[i] >= r) { s_sel[0] = (uint32_t)(hi - i);
                                            s_sel[1] = r - c2; break; }
                    c2 += cnt[i];
                }
            }
        }
        __syncthreads();
        prefix |= s_sel[0] << shift;
        rem = s_sel[1];
        __syncthreads();
    }

    const uint32_t tkey = prefix;
    const float thr = (tkey & 0x80000000u)
                    ? __uint_as_float(tkey ^ 0x80000000u)
                    : __uint_as_float(~tkey);
    const float sg = (k0 > tkey ? sc0 : 0.0f) + (k1 > tkey ? sc1 : 0.0f);
    const float sum_gt = block_sum(sg, s_red);
    const float tsum = sum_gt + (float)rem * thr;

    if (tid == 0)
        out[b] = (T > 0) ? 0.5f * attn + 0.5f * (tsum / (float)kk) : 0.0f;
}

// ---------------------------------------------------------------------------
extern "C" void kernel_launch(void* const* d_in, const int* in_sizes, int n_in,
                              void* d_out, int out_size) {
    const float* x    = (const float*)d_in[0];
    const int*   lens = (const int*)  d_in[1];
    const float* W1   = (const float*)d_in[2];
    const float* b1   = (const float*)d_in[3];
    const float* ln_g = (const float*)d_in[4];
    const float* ln_b = (const float*)d_in[5];
    const float* Wa1  = (const float*)d_in[6];
    const float* ba1  = (const float*)d_in[7];
    const float* Wa2  = (const float*)d_in[8];
    const float* ba2  = (const float*)d_in[9];
    const float* Wc   = (const float*)d_in[10];
    const float* bc   = (const float*)d_in[11];
    float* out = (float*)d_out;

    // idempotent, executes immediately (not stream-captured)
    cudaFuncSetAttribute(gemm1_kernel,
                         cudaFuncAttributeMaxDynamicSharedMemorySize, SM1);
    cudaFuncSetAttribute(gemm2_kernel,
                         cudaFuncAttributeMaxDynamicSharedMemorySize, SM2);

    convert_w1_kernel<<<HDIM * DDIM / 1024, 256>>>(W1);
    convert_wa_kernel<<<ADIM * HDIM / 1024, 256>>>(Wa1);
    gemm1_kernel<<<MTOT / 64, 256, SM1>>>(x, b1, ln_g, ln_b, Wc, bc, out);
    gemm2_kernel<<<MTOT / 64, 256, SM2>>>(ba1, Wa2, ba2);
    finalize_kernel<<<BB, 1024>>>(lens, out);
}

// round 14
// speedup vs baseline: 1.3591x; 1.0434x over previous
#include <cuda_runtime.h>
#include <cuda_fp16.h>
#include <math.h>
#include <cstdint>

#define MTOT 32768   // B*N rows
#define DDIM 1024
#define HDIM 256
#define ADIM 128
#define BB   16
#define NN   2048
#define NEGV (-1e9f)

// ---------------------------------------------------------------------------
// Scratch (__device__ globals; allocation-free rule)
// ---------------------------------------------------------------------------
__device__ __align__(1024) __half g_wh[(size_t)HDIM * DDIM];    // W1 fp16
__device__ __align__(1024) __half g_wah[(size_t)ADIM * HDIM];   // Wa1 fp16
__device__ __align__(1024) __half g_hf[(size_t)MTOT * HDIM];    // h fp16
__device__ __align__(1024) float  g_logits[MTOT];

// ---------------------------------------------------------------------------
// Helpers (base sm_100 target: mma.sync / ldmatrix / cp.async only)
// ---------------------------------------------------------------------------
__device__ __forceinline__ uint32_t smem_u32(const void* p) {
    uint32_t r;
    asm("{ .reg .u64 t; cvta.to.shared.u64 t, %1; cvt.u32.u64 %0, t; }"
        : "=r"(r) : "l"(p));
    return r;
}
__device__ __forceinline__ void cpa16(uint32_t dst, const void* src) {
    asm volatile("cp.async.cg.shared.global [%0], [%1], 16;"
                 :: "r"(dst), "l"(src) : "memory");
}
#define CP_COMMIT() asm volatile("cp.async.commit_group;" ::: "memory")
#define CP_WAIT0()  asm volatile("cp.async.wait_group 0;" ::: "memory")
#define CP_WAIT1()  asm volatile("cp.async.wait_group 1;" ::: "memory")

__device__ __forceinline__ void ldsm4(uint32_t* r, uint32_t a) {
    asm volatile("ldmatrix.sync.aligned.m8n8.x4.shared.b16 {%0,%1,%2,%3}, [%4];"
                 : "=r"(r[0]), "=r"(r[1]), "=r"(r[2]), "=r"(r[3]) : "r"(a));
}
__device__ __forceinline__ void mmah(float* c, const uint32_t* a,
                                     uint32_t b0, uint32_t b1) {
    asm volatile(
        "mma.sync.aligned.m16n8k16.row.col.f32.f16.f16.f32 "
        "{%0,%1,%2,%3}, {%4,%5,%6,%7}, {%8,%9}, {%0,%1,%2,%3};"
        : "+f"(c[0]), "+f"(c[1]), "+f"(c[2]), "+f"(c[3])
        : "r"(a[0]), "r"(a[1]), "r"(a[2]), "r"(a[3]), "r"(b0), "r"(b1));
}
__device__ __forceinline__ uint32_t sw64(uint32_t off) {
    return off ^ ((off >> 3) & 0x30);
}
__device__ __forceinline__ uint32_t sw128(uint32_t off) {
    return off ^ ((off >> 3) & 0x70);
}
__device__ __forceinline__ uint32_t pkh2(__half a, __half b) {
    __half2 t = __halves2half2(a, b);   // .x = a = low 16 bits
    return *reinterpret_cast<uint32_t*>(&t);
}
__device__ __forceinline__ float gelu_exact(float y) {
    return 0.5f * y * (1.0f + erff(y * 0.70710678118654752f));
}

// ---------------------------------------------------------------------------
// Weight conversion (f32 -> fp16)
// ---------------------------------------------------------------------------
__global__ __launch_bounds__(256) void convert_w1_kernel(const float* __restrict__ s) {
    size_t i = (size_t)blockIdx.x * 256 + threadIdx.x;
    float4 v = reinterpret_cast<const float4*>(s)[i];
    __half2* dst = reinterpret_cast<__half2*>(g_wh);
    dst[2 * i]     = __floats2half2_rn(v.x, v.y);
    dst[2 * i + 1] = __floats2half2_rn(v.z, v.w);
}
__global__ __launch_bounds__(256) void convert_wa_kernel(const float* __restrict__ s) {
    size_t i = (size_t)blockIdx.x * 256 + threadIdx.x;
    float4 v = reinterpret_cast<const float4*>(s)[i];
    __half2* dst = reinterpret_cast<__half2*>(g_wah);
    dst[2 * i]     = __floats2half2_rn(v.x, v.y);
    dst[2 * i + 1] = __floats2half2_rn(v.z, v.w);
}

// ---------------------------------------------------------------------------
// GEMM1 + LN + GELU + instance score, fused.
// C = x(32768x1024) @ W1^T(1024x256): BM=64, BN=256(full), KC=32, 256 thr.
// Single-pass fp16. Joint 4-STAGE cp.async pipeline for W (fp16) AND x (f32);
// issue-before-wait is safe with N=4: stage written at iter c last held
// chunk c-2, whose reads completed before iter c-1's barrier.
// x converted smem->smem one chunk ahead (LDS latency, fully covered).
// SMEM: W 4x16K [0,64K); Af32 4x8K [64K,96K); Afp16 2x4K [96K,104K).
// Epilogue sacc f32 64x260 (66.5K) aliases [0,66.5K). SM1 = 106496.
// ---------------------------------------------------------------------------
#define W1OFF  0
#define AF32   65536
#define AH16   98304
#define SM1    106496

__device__ __forceinline__ void cp_w1(uint32_t stage_base, int c) {
    const int t = threadIdx.x;
    #pragma unroll
    for (int i = 0; i < 4; i++) {
        int a = t + i * 256;           // atom 0..1023: 256 n-rows x 4 atoms
        int row = a >> 2, ac = a & 3;
        uint32_t sw = sw64(row * 64 + ac * 16);
        cpa16(stage_base + sw, g_wh + (size_t)row * DDIM + c * 32 + ac * 8);
    }
}
__device__ __forceinline__ void cp_a1(uint32_t stage_base, int c, int bm,
                                      const float* __restrict__ x) {
    const int t = threadIdx.x;
    #pragma unroll
    for (int i = 0; i < 2; i++) {      // 512 granules: 64 rows x 8 (128B rows)
        int g = t + i * 256;
        int row = g >> 3, gc = g & 7;
        uint32_t sw = sw128(row * 128 + gc * 16);
        cpa16(stage_base + sw, x + (size_t)(bm + row) * DDIM + c * 32 + gc * 4);
    }
}
// convert f32 chunk (in Af32 stage) -> fp16 buffer
__device__ __forceinline__ void cvt_a1(char* smem, uint32_t f32stg, uint32_t h16stg) {
    const int t = threadIdx.x;
    const int row = t >> 2;
    const int gc = (t & 3) * 2;
    float4 q0 = *(const float4*)(smem + f32stg + sw128(row * 128 + gc * 16));
    float4 q1 = *(const float4*)(smem + f32stg + sw128(row * 128 + gc * 16 + 16));
    uint4 hv;
    uint32_t* hp = (uint32_t*)&hv;
    hp[0] = pkh2(__float2half_rn(q0.x), __float2half_rn(q0.y));
    hp[1] = pkh2(__float2half_rn(q0.z), __float2half_rn(q0.w));
    hp[2] = pkh2(__float2half_rn(q1.x), __float2half_rn(q1.y));
    hp[3] = pkh2(__float2half_rn(q1.z), __float2half_rn(q1.w));
    *(uint4*)(smem + h16stg + sw64((uint32_t)(row * 64 + gc * 8))) = hv;
}

__global__ __launch_bounds__(256, 2) void gemm1_kernel(
        const float* __restrict__ x, const float* __restrict__ b1,
        const float* __restrict__ ln_g, const float* __restrict__ ln_b,
        const float* __restrict__ Wc, const float* __restrict__ bc,
        float* __restrict__ out) {
    extern __shared__ __align__(1024) char smem[];
    const uint32_t sbu = smem_u32(smem);
    const int tid = threadIdx.x, lane = tid & 31, wid = tid >> 5;
    const int bm = blockIdx.x * 64;

    {   // prologue: groups 0 and 1 in flight; convert chunk 0 to fp16 buf 0
        cp_w1(sbu + W1OFF, 0);
        cp_a1(sbu + AF32, 0, bm, x);
        CP_COMMIT();
        cp_w1(sbu + W1OFF + 16384, 1);
        cp_a1(sbu + AF32 + 8192, 1, bm, x);
        CP_COMMIT();
        CP_WAIT1();          // group 0 resident
        __syncthreads();
        cvt_a1(smem, AF32, AH16);
    }

    float acc[4][4][4];
    #pragma unroll
    for (int i = 0; i < 4; i++)
        #pragma unroll
        for (int j = 0; j < 4; j++)
            #pragma unroll
            for (int k = 0; k < 4; k++) acc[i][j][k] = 0.0f;

    const int n0 = wid * 32;

    for (int c = 0; c < 32; c++) {
        const uint32_t astg = AH16 + (uint32_t)(c & 1) * 4096;
        const uint32_t wstg = W1OFF + (uint32_t)(c & 3) * 16384;
        if (c + 2 < 32) {    // issue group c+2 (stage (c+2)%4: safe, held c-2)
            cp_w1(sbu + W1OFF + (uint32_t)((c + 2) & 3) * 16384, c + 2);
            cp_a1(sbu + AF32 + (uint32_t)((c + 2) & 3) * 8192, c + 2, bm, x);
            CP_COMMIT();
            CP_WAIT1();      // groups <= c+1 resident
        } else {
            CP_WAIT0();
        }
        __syncthreads();
        if (c + 1 < 32)      // convert next chunk's x (smem->smem, covered)
            cvt_a1(smem, AF32 + (uint32_t)((c + 1) & 3) * 8192,
                   AH16 + (uint32_t)((c + 1) & 1) * 4096);
        #pragma unroll
        for (int k16 = 0; k16 < 2; k16++) {
            uint32_t aF[4][4], bF[2][4];
            #pragma unroll
            for (int mt = 0; mt < 4; mt++) {
                uint32_t off = (uint32_t)((mt * 16 + ((lane >> 3) & 1) * 8 + (lane & 7)) * 64
                               + k16 * 32 + ((lane >> 4) & 1) * 16);
                ldsm4(aF[mt], sbu + astg + sw64(off));
            }
            #pragma unroll
            for (int bp = 0; bp < 2; bp++) {
                uint32_t off = (uint32_t)((n0 + bp * 16 + ((lane >> 4) & 1) * 8 + (lane & 7)) * 64
                               + k16 * 32 + ((lane >> 3) & 1) * 16);
                ldsm4(bF[bp], sbu + wstg + sw64(off));
            }
            #pragma unroll
            for (int mt = 0; mt < 4; mt++)
                #pragma unroll
                for (int nt = 0; nt < 4; nt++)
                    mmah(acc[mt][nt], aF[mt],
                         bF[nt >> 1][(nt & 1) * 2], bF[nt >> 1][(nt & 1) * 2 + 1]);
        }
    }
    __syncthreads();

    // ---- epilogue: stage accums (64 x 256, stride 260), per-row LN+GELU ----
    float* sacc = (float*)smem;
    #pragma unroll
    for (int mt = 0; mt < 4; mt++)
        #pragma unroll
        for (int nt = 0; nt < 4; nt++) {
            int row = mt * 16 + (lane >> 2);
            int col = n0 + nt * 8 + (lane & 3) * 2;
            sacc[row * 260 + col]           = acc[mt][nt][0];
            sacc[row * 260 + col + 1]       = acc[mt][nt][1];
            sacc[(row + 8) * 260 + col]     = acc[mt][nt][2];
            sacc[(row + 8) * 260 + col + 1] = acc[mt][nt][3];
        }
    __syncthreads();

    #pragma unroll 1
    for (int it = 0; it < 8; it++) {
        const int row = it * 8 + wid;
        const int grow = bm + row;
        float v[8], s = 0.0f, q = 0.0f;
        #pragma unroll
        for (int i = 0; i < 8; i++) {
            int col = lane + 32 * i;
            v[i] = sacc[row * 260 + col] + __ldg(b1 + col);
            s += v[i]; q += v[i] * v[i];
        }
        #pragma unroll
        for (int o = 16; o; o >>= 1) {
            s += __shfl_xor_sync(0xffffffffu, s, o);
            q += __shfl_xor_sync(0xffffffffu, q, o);
        }
        const float mean = s * (1.0f / 256.0f);
        const float var  = q * (1.0f / 256.0f) - mean * mean;
        const float rstd = rsqrtf(var + 1e-5f);
        float sc = 0.0f;
        #pragma unroll
        for (int i = 0; i < 8; i++) {
            int col = lane + 32 * i;
            float y = (v[i] - mean) * rstd * __ldg(ln_g + col) + __ldg(ln_b + col);
            y = gelu_exact(y);
            sc += y * __ldg(Wc + col);
            g_hf[(size_t)grow * HDIM + col] = __float2half_rn(y);
        }
        #pragma unroll
        for (int o = 16; o; o >>= 1) sc += __shfl_xor_sync(0xffffffffu, sc, o);
        if (lane == 0) out[BB + grow] = sc + __ldg(bc);
    }
}

// ---------------------------------------------------------------------------
// GEMM2 + tanh + Wa2 reduce, fused.  logits = tanh(h@Wa1^T + ba1).Wa2 + ba2
// M=32768, N=128(full), K=256: BM=64, BN=128, KC=32, 256 thr (2m x 4n warps)
// 3-stage pipeline (issue AFTER sync -> race-free at N=3). SM2 = 36864.
// ---------------------------------------------------------------------------
#define SM2 36864

__device__ __forceinline__ void cp_h2(uint32_t stage_base, int c, int bm) {
    const int t = threadIdx.x;
    {   // A: 64 rows x 4 atoms = 256
        int row = t >> 2, ac = t & 3;
        uint32_t sw = sw64(row * 64 + ac * 16);
        cpa16(stage_base + sw, g_hf + (size_t)(bm + row) * HDIM + c * 32 + ac * 8);
    }
    #pragma unroll
    for (int i = 0; i < 2; i++) {      // B: 128 rows x 4 atoms = 512
        int a = t + i * 256;
        int row = a >> 2, ac = a & 3;
        uint32_t sw = sw64(row * 64 + ac * 16);
        cpa16(stage_base + 4096 + sw, g_wah + (size_t)row * HDIM + c * 32 + ac * 8);
    }
}

__global__ __launch_bounds__(256, 2) void gemm2_kernel(
        const float* __restrict__ ba1, const float* __restrict__ Wa2,
        const float* __restrict__ ba2) {
    extern __shared__ __align__(1024) char smem[];
    const uint32_t sbu = smem_u32(smem);
    const int tid = threadIdx.x, lane = tid & 31, wid = tid >> 5;
    const int bm = blockIdx.x * 64;
    const int m0 = (wid >> 2) * 32, n0 = (wid & 3) * 32;

    cp_h2(sbu, 0, bm);
    CP_COMMIT();
    cp_h2(sbu + 12288, 1, bm);
    CP_COMMIT();

    float acc[2][4][4];
    #pragma unroll
    for (int i = 0; i < 2; i++)
        #pragma unroll
        for (int j = 0; j < 4; j++)
            #pragma unroll
            for (int k = 0; k < 4; k++) acc[i][j][k] = 0.0f;

    for (int c = 0; c < 8; c++) {
        const uint32_t stg = (uint32_t)(c % 3) * 12288;
        if (c < 7) { CP_WAIT1(); } else { CP_WAIT0(); }
        __syncthreads();
        if (c < 6) {
            cp_h2(sbu + (uint32_t)((c + 2) % 3) * 12288, c + 2, bm);
            CP_COMMIT();
        }
        #pragma unroll
        for (int k16 = 0; k16 < 2; k16++) {
            uint32_t aF[2][4], bF[2][4];
            #pragma unroll
            for (int mt = 0; mt < 2; mt++) {
                uint32_t off = (uint32_t)((m0 + mt * 16 + ((lane >> 3) & 1) * 8 + (lane & 7)) * 64
                               + k16 * 32 + ((lane >> 4) & 1) * 16);
                ldsm4(aF[mt], sbu + stg + sw64(off));
            }
            #pragma unroll
            for (int bp = 0; bp < 2; bp++) {
                uint32_t off = (uint32_t)((n0 + bp * 16 + ((lane >> 4) & 1) * 8 + (lane & 7)) * 64
                               + k16 * 32 + ((lane >> 3) & 1) * 16);
                ldsm4(bF[bp], sbu + stg + 4096 + sw64(off));
            }
            #pragma unroll
            for (int mt = 0; mt < 2; mt++)
                #pragma unroll
                for (int nt = 0; nt < 4; nt++)
                    mmah(acc[mt][nt], aF[mt],
                         bF[nt >> 1][(nt & 1) * 2], bF[nt >> 1][(nt & 1) * 2 + 1]);
        }
    }
    __syncthreads();

    // ---- epilogue: tanh(.+ba1)*Wa2, reduce over n, cross-warp via smem ----
    float* spart = (float*)smem;   // [64][5] padded
    #pragma unroll
    for (int mt = 0; mt < 2; mt++) {
        float r0 = 0.0f, r1 = 0.0f;
        #pragma unroll
        for (int nt = 0; nt < 4; nt++) {
            int col = n0 + nt * 8 + (lane & 3) * 2;
            float w0 = __ldg(Wa2 + col), w1 = __ldg(Wa2 + col + 1);
            float e0 = __ldg(ba1 + col), e1 = __ldg(ba1 + col + 1);
            r0 += tanhf(acc[mt][nt][0] + e0) * w0 + tanhf(acc[mt][nt][1] + e1) * w1;
            r1 += tanhf(acc[mt][nt][2] + e0) * w0 + tanhf(acc[mt][nt][3] + e1) * w1;
        }
        r0 += __shfl_xor_sync(0xffffffffu, r0, 1);
        r0 += __shfl_xor_sync(0xffffffffu, r0, 2);
        r1 += __shfl_xor_sync(0xffffffffu, r1, 1);
        r1 += __shfl_xor_sync(0xffffffffu, r1, 2);
        if ((lane & 3) == 0) {
            int row = m0 + mt * 16 + (lane >> 2);
            spart[row * 5 + (wid & 3)]       = r0;
            spart[(row + 8) * 5 + (wid & 3)] = r1;
        }
    }
    __syncthreads();
    if (tid < 64) {
        float v = spart[tid * 5 + 0] + spart[tid * 5 + 1]
                + spart[tid * 5 + 2] + spart[tid * 5 + 3] + __ldg(ba2);
        g_logits[bm + tid] = v;
    }
}

// ---------------------------------------------------------------------------
// Finalize: masked softmax pooling + dynamic top-k via 4-round radix-select
// ---------------------------------------------------------------------------
__device__ __forceinline__ float block_sum(float v, float* red) {
    const int lane = threadIdx.x & 31, warp = threadIdx.x >> 5;
    #pragma unroll
    for (int o = 16; o; o >>= 1) v += __shfl_xor_sync(0xffffffffu, v, o);
    __syncthreads();
    if (lane == 0) red[warp] = v;
    __syncthreads();
    if (warp == 0) {
        float t = red[lane];
        #pragma unroll
        for (int o = 16; o; o >>= 1) t += __shfl_xor_sync(0xffffffffu, t, o);
        if (lane == 0) red[0] = t;
    }
    __syncthreads();
    return red[0];
}
__device__ __forceinline__ float block_max(float v, float* red) {
    const int lane = threadIdx.x & 31, warp = threadIdx.x >> 5;
    #pragma unroll
    for (int o = 16; o; o >>= 1)
        v = fmaxf(v, __shfl_xor_sync(0xffffffffu, v, o));
    __syncthreads();
    if (lane == 0) red[warp] = v;
    __syncthreads();
    if (warp == 0) {
        float t = red[lane];
        #pragma unroll
        for (int o = 16; o; o >>= 1)
            t = fmaxf(t, __shfl_xor_sync(0xffffffffu, t, o));
        if (lane == 0) red[0] = t;
    }
    __syncthreads();
    return red[0];
}
__device__ __forceinline__ uint32_t fkey(float f, bool valid) {
    uint32_t u = __float_as_uint(f);
    u = (u & 0x80000000u) ? ~u : (u | 0x80000000u);
    return valid ? u : 0u;
}

__global__ __launch_bounds__(1024) void finalize_kernel(
        const int* __restrict__ lengths, float* __restrict__ out) {
    __shared__ float s_red[32];
    __shared__ uint32_t s_hist[256];
    __shared__ uint32_t s_sel[2];
    const int b = blockIdx.x, tid = threadIdx.x;
    const int T = lengths[b];
    const float* scores = out + BB + (size_t)b * NN;
    const float* logits = g_logits + (size_t)b * NN;

    const float sc0 = scores[tid],        sc1 = scores[tid + 1024];
    const float lg0 = logits[tid],        lg1 = logits[tid + 1024];
    const bool  v0  = tid < T,            v1  = (tid + 1024) < T;
    const float ml0 = v0 ? lg0 : NEGV,    ml1 = v1 ? lg1 : NEGV;

    const float mx  = block_max(fmaxf(ml0, ml1), s_red);
    const float e0  = expf(ml0 - mx), e1 = expf(ml1 - mx);
    const float den = block_sum(e0 + e1, s_red);
    const float num = block_sum((v0 ? e0 * sc0 : 0.0f) +
                                (v1 ? e1 * sc1 : 0.0f), s_red);
    const float attn = num / den;

    // ---- radix-select k-th largest (exact, with tie handling) ----
    const uint32_t k0 = fkey(sc0, v0), k1 = fkey(sc1, v1);
    int kk = T / 10;
    if (kk < 1) kk = 1;
    uint32_t prefix = 0, rem = (uint32_t)kk;

    #pragma unroll 1
    for (int shift = 24; shift >= 0; shift -= 8) {
        if (tid < 256) s_hist[tid] = 0;
        __syncthreads();
        const uint32_t msk = (shift == 24) ? 0u : (0xFFFFFFFFu << (shift + 8));
        if ((k0 & msk) == prefix) atomicAdd(&s_hist[(k0 >> shift) & 255], 1u);
        if ((k1 & msk) == prefix) atomicAdd(&s_hist[(k1 >> shift) & 255], 1u);
        __syncthreads();
        if (tid < 32) {
            const int hi = 255 - tid * 8;
            uint32_t cnt[8], csum = 0;
            #pragma unroll
            for (int i = 0; i < 8; i++) { cnt[i] = s_hist[hi - i]; csum += cnt[i]; }
            uint32_t run = csum;
            #pragma unroll
            for (int o = 1; o < 32; o <<= 1) {
                uint32_t t = __shfl_up_sync(0xffffffffu, run, o);
                if (tid >= o) run += t;
            }
            const uint32_t excl = run - csum;
            if (excl < rem && rem <= excl + csum) {
                uint32_t r = rem - excl, c2 = 0;
                #pragma unroll
                for (int i = 0; i < 8; i++) {
                    if (c2 + cnt[i] >= r) { s_sel[0] = (uint32_t)(hi - i);
                                            s_sel[1] = r - c2; break; }
                    c2 += cnt[i];
                }
            }
        }
        __syncthreads();
        prefix |= s_sel[0] << shift;
        rem = s_sel[1];
        __syncthreads();
    }

    const uint32_t tkey = prefix;
    const float thr = (tkey & 0x80000000u)
                    ? __uint_as_float(tkey ^ 0x80000000u)
                    : __uint_as_float(~tkey);
    const float sg = (k0 > tkey ? sc0 : 0.0f) + (k1 > tkey ? sc1 : 0.0f);
    const float sum_gt = block_sum(sg, s_red);
    const float tsum = sum_gt + (float)rem * thr;

    if (tid == 0)
        out[b] = (T > 0) ? 0.5f * attn + 0.5f * (tsum / (float)kk) : 0.0f;
}

// ---------------------------------------------------------------------------
extern "C" void kernel_launch(void* const* d_in, const int* in_sizes, int n_in,
                              void* d_out, int out_size) {
    const float* x    = (const float*)d_in[0];
    const int*   lens = (const int*)  d_in[1];
    const float* W1   = (const float*)d_in[2];
    const float* b1   = (const float*)d_in[3];
    const float* ln_g = (const float*)d_in[4];
    const float* ln_b = (const float*)d_in[5];
    const float* Wa1  = (const float*)d_in[6];
    const float* ba1  = (const float*)d_in[7];
    const float* Wa2  = (const float*)d_in[8];
    const float* ba2  = (const float*)d_in[9];
    const float* Wc   = (const float*)d_in[10];
    const float* bc   = (const float*)d_in[11];
    float* out = (float*)d_out;

    // idempotent, executes immediately (not stream-captured)
    cudaFuncSetAttribute(gemm1_kernel,
                         cudaFuncAttributeMaxDynamicSharedMemorySize, SM1);
    cudaFuncSetAttribute(gemm2_kernel,
                         cudaFuncAttributeMaxDynamicSharedMemorySize, SM2);

    convert_w1_kernel<<<HDIM * DDIM / 1024, 256>>>(W1);
    convert_wa_kernel<<<ADIM * HDIM / 1024, 256>>>(Wa1);
    gemm1_kernel<<<MTOT / 64, 256, SM1>>>(x, b1, ln_g, ln_b, Wc, bc, out);
    gemm2_kernel<<<MTOT / 64, 256, SM2>>>(ba1, Wa2, ba2);
    finalize_kernel<<<BB, 1024>>>(lens, out);
}

// round 15
// speedup vs baseline: 1.3899x; 1.0227x over previous
#include <cuda_runtime.h>
#include <cuda_fp16.h>
#include <math.h>
#include <cstdint>

#define MTOT 32768   // B*N rows
#define DDIM 1024
#define HDIM 256
#define ADIM 128
#define BB   16
#define NN   2048
#define NEGV (-1e9f)

// ---------------------------------------------------------------------------
// Scratch (__device__ globals; allocation-free rule)
// ---------------------------------------------------------------------------
__device__ __align__(1024) __half g_wh[(size_t)HDIM * DDIM];    // W1 fp16
__device__ __align__(1024) __half g_wah[(size_t)ADIM * HDIM];   // Wa1 fp16
__device__ __align__(1024) __half g_hf[(size_t)MTOT * HDIM];    // h fp16
__device__ __align__(1024) float  g_logits[MTOT];

// ---------------------------------------------------------------------------
// Helpers (base sm_100 target: mma.sync / ldmatrix / cp.async only)
// ---------------------------------------------------------------------------
__device__ __forceinline__ uint32_t smem_u32(const void* p) {
    uint32_t r;
    asm("{ .reg .u64 t; cvta.to.shared.u64 t, %1; cvt.u32.u64 %0, t; }"
        : "=r"(r) : "l"(p));
    return r;
}
__device__ __forceinline__ void cpa16(uint32_t dst, const void* src) {
    asm volatile("cp.async.cg.shared.global [%0], [%1], 16;"
                 :: "r"(dst), "l"(src) : "memory");
}
#define CP_COMMIT() asm volatile("cp.async.commit_group;" ::: "memory")
#define CP_WAIT0()  asm volatile("cp.async.wait_group 0;" ::: "memory")
#define CP_WAIT1()  asm volatile("cp.async.wait_group 1;" ::: "memory")

__device__ __forceinline__ void ldsm4(uint32_t* r, uint32_t a) {
    asm volatile("ldmatrix.sync.aligned.m8n8.x4.shared.b16 {%0,%1,%2,%3}, [%4];"
                 : "=r"(r[0]), "=r"(r[1]), "=r"(r[2]), "=r"(r[3]) : "r"(a));
}
__device__ __forceinline__ void mmah(float* c, const uint32_t* a,
                                     uint32_t b0, uint32_t b1) {
    asm volatile(
        "mma.sync.aligned.m16n8k16.row.col.f32.f16.f16.f32 "
        "{%0,%1,%2,%3}, {%4,%5,%6,%7}, {%8,%9}, {%0,%1,%2,%3};"
        : "+f"(c[0]), "+f"(c[1]), "+f"(c[2]), "+f"(c[3])
        : "r"(a[0]), "r"(a[1]), "r"(a[2]), "r"(a[3]), "r"(b0), "r"(b1));
}
__device__ __forceinline__ uint32_t sw64(uint32_t off) {
    return off ^ ((off >> 3) & 0x30);
}
__device__ __forceinline__ uint32_t sw128(uint32_t off) {
    return off ^ ((off >> 3) & 0x70);
}
__device__ __forceinline__ uint32_t pkh2(__half a, __half b) {
    __half2 t = __halves2half2(a, b);   // .x = a = low 16 bits
    return *reinterpret_cast<uint32_t*>(&t);
}
__device__ __forceinline__ float gelu_exact(float y) {
    return 0.5f * y * (1.0f + erff(y * 0.70710678118654752f));
}

// ---------------------------------------------------------------------------
// Weight conversion (f32 -> fp16): single merged kernel.
// Blocks [0,256): W1 (256K f32); blocks [256,288): Wa1 (32K f32).
// ---------------------------------------------------------------------------
__global__ __launch_bounds__(256) void convert_weights_kernel(
        const float* __restrict__ W1, const float* __restrict__ Wa1) {
    if (blockIdx.x < 256) {
        size_t i = (size_t)blockIdx.x * 256 + threadIdx.x;
        float4 v = reinterpret_cast<const float4*>(W1)[i];
        __half2* dst = reinterpret_cast<__half2*>(g_wh);
        dst[2 * i]     = __floats2half2_rn(v.x, v.y);
        dst[2 * i + 1] = __floats2half2_rn(v.z, v.w);
    } else {
        size_t i = (size_t)(blockIdx.x - 256) * 256 + threadIdx.x;
        float4 v = reinterpret_cast<const float4*>(Wa1)[i];
        __half2* dst = reinterpret_cast<__half2*>(g_wah);
        dst[2 * i]     = __floats2half2_rn(v.x, v.y);
        dst[2 * i + 1] = __floats2half2_rn(v.z, v.w);
    }
}

// ---------------------------------------------------------------------------
// GEMM1 + LN + GELU + instance score, fused.
// C = x(32768x1024) @ W1^T(1024x256): BM=64, BN=256(full), KC=32, 256 thr.
// Single-pass fp16. Joint 4-STAGE cp.async pipeline for W (fp16) AND x (f32);
// issue-before-wait safe at N=4 (stage written at iter c last held chunk c-2,
// whose reads completed before iter c-1's barrier).
// x converted smem->smem one chunk ahead (LDS latency, fully covered).
// SMEM: W 4x16K [0,64K); Af32 4x8K [64K,96K); Afp16 2x4K [96K,104K).
// Epilogue sacc f32 64x260 (66.5K) aliases [0,66.5K). SM1 = 106496.
// ---------------------------------------------------------------------------
#define W1OFF  0
#define AF32   65536
#define AH16   98304
#define SM1    106496

__device__ __forceinline__ void cp_w1(uint32_t stage_base, int c) {
    const int t = threadIdx.x;
    #pragma unroll
    for (int i = 0; i < 4; i++) {
        int a = t + i * 256;           // atom 0..1023: 256 n-rows x 4 atoms
        int row = a >> 2, ac = a & 3;
        uint32_t sw = sw64(row * 64 + ac * 16);
        cpa16(stage_base + sw, g_wh + (size_t)row * DDIM + c * 32 + ac * 8);
    }
}
__device__ __forceinline__ void cp_a1(uint32_t stage_base, int c, int bm,
                                      const float* __restrict__ x) {
    const int t = threadIdx.x;
    #pragma unroll
    for (int i = 0; i < 2; i++) {      // 512 granules: 64 rows x 8 (128B rows)
        int g = t + i * 256;
        int row = g >> 3, gc = g & 7;
        uint32_t sw = sw128(row * 128 + gc * 16);
        cpa16(stage_base + sw, x + (size_t)(bm + row) * DDIM + c * 32 + gc * 4);
    }
}
// convert f32 chunk (in Af32 stage) -> fp16 buffer
__device__ __forceinline__ void cvt_a1(char* smem, uint32_t f32stg, uint32_t h16stg) {
    const int t = threadIdx.x;
    const int row = t >> 2;
    const int gc = (t & 3) * 2;
    float4 q0 = *(const float4*)(smem + f32stg + sw128(row * 128 + gc * 16));
    float4 q1 = *(const float4*)(smem + f32stg + sw128(row * 128 + gc * 16 + 16));
    uint4 hv;
    uint32_t* hp = (uint32_t*)&hv;
    hp[0] = pkh2(__float2half_rn(q0.x), __float2half_rn(q0.y));
    hp[1] = pkh2(__float2half_rn(q0.z), __float2half_rn(q0.w));
    hp[2] = pkh2(__float2half_rn(q1.x), __float2half_rn(q1.y));
    hp[3] = pkh2(__float2half_rn(q1.z), __float2half_rn(q1.w));
    *(uint4*)(smem + h16stg + sw64((uint32_t)(row * 64 + gc * 8))) = hv;
}

__global__ __launch_bounds__(256, 2) void gemm1_kernel(
        const float* __restrict__ x, const float* __restrict__ b1,
        const float* __restrict__ ln_g, const float* __restrict__ ln_b,
        const float* __restrict__ Wc, const float* __restrict__ bc,
        float* __restrict__ out) {
    extern __shared__ __align__(1024) char smem[];
    const uint32_t sbu = smem_u32(smem);
    const int tid = threadIdx.x, lane = tid & 31, wid = tid >> 5;
    const int bm = blockIdx.x * 64;

    {   // prologue: groups 0 and 1 in flight; convert chunk 0 to fp16 buf 0
        cp_w1(sbu + W1OFF, 0);
        cp_a1(sbu + AF32, 0, bm, x);
        CP_COMMIT();
        cp_w1(sbu + W1OFF + 16384, 1);
        cp_a1(sbu + AF32 + 8192, 1, bm, x);
        CP_COMMIT();
        CP_WAIT1();          // group 0 resident
        __syncthreads();
        cvt_a1(smem, AF32, AH16);
    }

    float acc[4][4][4];
    #pragma unroll
    for (int i = 0; i < 4; i++)
        #pragma unroll
        for (int j = 0; j < 4; j++)
            #pragma unroll
            for (int k = 0; k < 4; k++) acc[i][j][k] = 0.0f;

    const int n0 = wid * 32;

    for (int c = 0; c < 32; c++) {
        const uint32_t astg = AH16 + (uint32_t)(c & 1) * 4096;
        const uint32_t wstg = W1OFF + (uint32_t)(c & 3) * 16384;
        if (c + 2 < 32) {    // issue group c+2 (stage (c+2)%4: safe, held c-2)
            cp_w1(sbu + W1OFF + (uint32_t)((c + 2) & 3) * 16384, c + 2);
            cp_a1(sbu + AF32 + (uint32_t)((c + 2) & 3) * 8192, c + 2, bm, x);
            CP_COMMIT();
            CP_WAIT1();      // groups <= c+1 resident
        } else {
            CP_WAIT0();
        }
        __syncthreads();
        if (c + 1 < 32)      // convert next chunk's x (smem->smem, covered)
            cvt_a1(smem, AF32 + (uint32_t)((c + 1) & 3) * 8192,
                   AH16 + (uint32_t)((c + 1) & 1) * 4096);
        #pragma unroll
        for (int k16 = 0; k16 < 2; k16++) {
            uint32_t aF[4][4], bF[2][4];
            #pragma unroll
            for (int mt = 0; mt < 4; mt++) {
                uint32_t off = (uint32_t)((mt * 16 + ((lane >> 3) & 1) * 8 + (lane & 7)) * 64
                               + k16 * 32 + ((lane >> 4) & 1) * 16);
                ldsm4(aF[mt], sbu + astg + sw64(off));
            }
            #pragma unroll
            for (int bp = 0; bp < 2; bp++) {
                uint32_t off = (uint32_t)((n0 + bp * 16 + ((lane >> 4) & 1) * 8 + (lane & 7)) * 64
                               + k16 * 32 + ((lane >> 3) & 1) * 16);
                ldsm4(bF[bp], sbu + wstg + sw64(off));
            }
            #pragma unroll
            for (int mt = 0; mt < 4; mt++)
                #pragma unroll
                for (int nt = 0; nt < 4; nt++)
                    mmah(acc[mt][nt], aF[mt],
                         bF[nt >> 1][(nt & 1) * 2], bF[nt >> 1][(nt & 1) * 2 + 1]);
        }
    }
    __syncthreads();

    // ---- epilogue: stage accums (64 x 256, stride 260), per-row LN+GELU ----
    float* sacc = (float*)smem;
    #pragma unroll
    for (int mt = 0; mt < 4; mt++)
        #pragma unroll
        for (int nt = 0; nt < 4; nt++) {
            int row = mt * 16 + (lane >> 2);
            int col = n0 + nt * 8 + (lane & 3) * 2;
            sacc[row * 260 + col]           = acc[mt][nt][0];
            sacc[row * 260 + col + 1]       = acc[mt][nt][1];
            sacc[(row + 8) * 260 + col]     = acc[mt][nt][2];
            sacc[(row + 8) * 260 + col + 1] = acc[mt][nt][3];
        }
    __syncthreads();

    #pragma unroll 1
    for (int it = 0; it < 8; it++) {
        const int row = it * 8 + wid;
        const int grow = bm + row;
        float v[8], s = 0.0f, q = 0.0f;
        #pragma unroll
        for (int i = 0; i < 8; i++) {
            int col = lane + 32 * i;
            v[i] = sacc[row * 260 + col] + __ldg(b1 + col);
            s += v[i]; q += v[i] * v[i];
        }
        #pragma unroll
        for (int o = 16; o; o >>= 1) {
            s += __shfl_xor_sync(0xffffffffu, s, o);
            q += __shfl_xor_sync(0xffffffffu, q, o);
        }
        const float mean = s * (1.0f / 256.0f);
        const float var  = q * (1.0f / 256.0f) - mean * mean;
        const float rstd = rsqrtf(var + 1e-5f);
        float sc = 0.0f;
        #pragma unroll
        for (int i = 0; i < 8; i++) {
            int col = lane + 32 * i;
            float y = (v[i] - mean) * rstd * __ldg(ln_g + col) + __ldg(ln_b + col);
            y = gelu_exact(y);
            sc += y * __ldg(Wc + col);
            g_hf[(size_t)grow * HDIM + col] = __float2half_rn(y);
        }
        #pragma unroll
        for (int o = 16; o; o >>= 1) sc += __shfl_xor_sync(0xffffffffu, sc, o);
        if (lane == 0) out[BB + grow] = sc + __ldg(bc);
    }
}

// ---------------------------------------------------------------------------
// GEMM2 + tanh + Wa2 reduce, fused.  logits = tanh(h@Wa1^T + ba1).Wa2 + ba2
// M=32768, N=128(full), K=256: BM=64, BN=128, KC=32, 256 thr (2m x 4n warps)
// 4-STAGE issue-before-wait pipeline (same safety proof as gemm1).
// Stage s at s*12288: A[+0,4K) B[+4K,12K). SM2 = 49152.
// ---------------------------------------------------------------------------
#define SM2 49152

__device__ __forceinline__ void cp_h2(uint32_t stage_base, int c, int bm) {
    const int t = threadIdx.x;
    {   // A: 64 rows x 4 atoms = 256
        int row = t >> 2, ac = t & 3;
        uint32_t sw = sw64(row * 64 + ac * 16);
        cpa16(stage_base + sw, g_hf + (size_t)(bm + row) * HDIM + c * 32 + ac * 8);
    }
    #pragma unroll
    for (int i = 0; i < 2; i++) {      // B: 128 rows x 4 atoms = 512
        int a = t + i * 256;
        int row = a >> 2, ac = a & 3;
        uint32_t sw = sw64(row * 64 + ac * 16);
        cpa16(stage_base + 4096 + sw, g_wah + (size_t)row * HDIM + c * 32 + ac * 8);
    }
}

__global__ __launch_bounds__(256, 2) void gemm2_kernel(
        const float* __restrict__ ba1, const float* __restrict__ Wa2,
        const float* __restrict__ ba2) {
    extern __shared__ __align__(1024) char smem[];
    const uint32_t sbu = smem_u32(smem);
    const int tid = threadIdx.x, lane = tid & 31, wid = tid >> 5;
    const int bm = blockIdx.x * 64;
    const int m0 = (wid >> 2) * 32, n0 = (wid & 3) * 32;

    cp_h2(sbu, 0, bm);
    CP_COMMIT();
    cp_h2(sbu + 12288, 1, bm);
    CP_COMMIT();

    float acc[2][4][4];
    #pragma unroll
    for (int i = 0; i < 2; i++)
        #pragma unroll
        for (int j = 0; j < 4; j++)
            #pragma unroll
            for (int k = 0; k < 4; k++) acc[i][j][k] = 0.0f;

    for (int c = 0; c < 8; c++) {
        const uint32_t stg = (uint32_t)(c & 3) * 12288;
        if (c + 2 < 8) {     // issue group c+2 (stage (c+2)&3 held chunk c-2)
            cp_h2(sbu + (uint32_t)((c + 2) & 3) * 12288, c + 2, bm);
            CP_COMMIT();
            CP_WAIT1();
        } else {
            CP_WAIT0();
        }
        __syncthreads();
        #pragma unroll
        for (int k16 = 0; k16 < 2; k16++) {
            uint32_t aF[2][4], bF[2][4];
            #pragma unroll
            for (int mt = 0; mt < 2; mt++) {
                uint32_t off = (uint32_t)((m0 + mt * 16 + ((lane >> 3) & 1) * 8 + (lane & 7)) * 64
                               + k16 * 32 + ((lane >> 4) & 1) * 16);
                ldsm4(aF[mt], sbu + stg + sw64(off));
            }
            #pragma unroll
            for (int bp = 0; bp < 2; bp++) {
                uint32_t off = (uint32_t)((n0 + bp * 16 + ((lane >> 4) & 1) * 8 + (lane & 7)) * 64
                               + k16 * 32 + ((lane >> 3) & 1) * 16);
                ldsm4(bF[bp], sbu + stg + 4096 + sw64(off));
            }
            #pragma unroll
            for (int mt = 0; mt < 2; mt++)
                #pragma unroll
                for (int nt = 0; nt < 4; nt++)
                    mmah(acc[mt][nt], aF[mt],
                         bF[nt >> 1][(nt & 1) * 2], bF[nt >> 1][(nt & 1) * 2 + 1]);
        }
    }
    __syncthreads();

    // ---- epilogue: tanh(.+ba1)*Wa2, reduce over n, cross-warp via smem ----
    float* spart = (float*)smem;   // [64][5] padded
    #pragma unroll
    for (int mt = 0; mt < 2; mt++) {
        float r0 = 0.0f, r1 = 0.0f;
        #pragma unroll
        for (int nt = 0; nt < 4; nt++) {
            int col = n0 + nt * 8 + (lane & 3) * 2;
            float w0 = __ldg(Wa2 + col), w1 = __ldg(Wa2 + col + 1);
            float e0 = __ldg(ba1 + col), e1 = __ldg(ba1 + col + 1);
            r0 += tanhf(acc[mt][nt][0] + e0) * w0 + tanhf(acc[mt][nt][1] + e1) * w1;
            r1 += tanhf(acc[mt][nt][2] + e0) * w0 + tanhf(acc[mt][nt][3] + e1) * w1;
        }
        r0 += __shfl_xor_sync(0xffffffffu, r0, 1);
        r0 += __shfl_xor_sync(0xffffffffu, r0, 2);
        r1 += __shfl_xor_sync(0xffffffffu, r1, 1);
        r1 += __shfl_xor_sync(0xffffffffu, r1, 2);
        if ((lane & 3) == 0) {
            int row = m0 + mt * 16 + (lane >> 2);
            spart[row * 5 + (wid & 3)]       = r0;
            spart[(row + 8) * 5 + (wid & 3)] = r1;
        }
    }
    __syncthreads();
    if (tid < 64) {
        float v = spart[tid * 5 + 0] + spart[tid * 5 + 1]
                + spart[tid * 5 + 2] + spart[tid * 5 + 3] + __ldg(ba2);
        g_logits[bm + tid] = v;
    }
}

// ---------------------------------------------------------------------------
// Finalize: masked softmax pooling + dynamic top-k via 4-round radix-select
// ---------------------------------------------------------------------------
__device__ __forceinline__ float block_sum(float v, float* red) {
    const int lane = threadIdx.x & 31, warp = threadIdx.x >> 5;
    #pragma unroll
    for (int o = 16; o; o >>= 1) v += __shfl_xor_sync(0xffffffffu, v, o);
    __syncthreads();
    if (lane == 0) red[warp] = v;
    __syncthreads();
    if (warp == 0) {
        float t = red[lane];
        #pragma unroll
        for (int o = 16; o; o >>= 1) t += __shfl_xor_sync(0xffffffffu, t, o);
        if (lane == 0) red[0] = t;
    }
    __syncthreads();
    return red[0];
}
// dual simultaneous block sum (saves one full barrier round-trip)
__device__ __forceinline__ float2 block_sum2(float a, float b, float* red) {
    const int lane = threadIdx.x & 31, warp = threadIdx.x >> 5;
    #pragma unroll
    for (int o = 16; o; o >>= 1) {
        a += __shfl_xor_sync(0xffffffffu, a, o);
        b += __shfl_xor_sync(0xffffffffu, b, o);
    }
    __syncthreads();
    if (lane == 0) { red[warp] = a; red[32 + warp] = b; }
    __syncthreads();
    if (warp == 0) {
        float ta = red[lane], tb = red[32 + lane];
        #pragma unroll
        for (int o = 16; o; o >>= 1) {
            ta += __shfl_xor_sync(0xffffffffu, ta, o);
            tb += __shfl_xor_sync(0xffffffffu, tb, o);
        }
        if (lane == 0) { red[0] = ta; red[1] = tb; }
    }
    __syncthreads();
    return make_float2(red[0], red[1]);
}
__device__ __forceinline__ float block_max(float v, float* red) {
    const int lane = threadIdx.x & 31, warp = threadIdx.x >> 5;
    #pragma unroll
    for (int o = 16; o; o >>= 1)
        v = fmaxf(v, __shfl_xor_sync(0xffffffffu, v, o));
    __syncthreads();
    if (lane == 0) red[warp] = v;
    __syncthreads();
    if (warp == 0) {
        float t = red[lane];
        #pragma unroll
        for (int o = 16; o; o >>= 1)
            t = fmaxf(t, __shfl_xor_sync(0xffffffffu, t, o));
        if (lane == 0) red[0] = t;
    }
    __syncthreads();
    return red[0];
}
__device__ __forceinline__ uint32_t fkey(float f, bool valid) {
    uint32_t u = __float_as_uint(f);
    u = (u & 0x80000000u) ? ~u : (u | 0x80000000u);
    return valid ? u : 0u;
}

__global__ __launch_bounds__(1024) void finalize_kernel(
        const int* __restrict__ lengths, float* __restrict__ out) {
    __shared__ float s_red[64];
    __shared__ uint32_t s_hist[256];
    __shared__ uint32_t s_sel[2];
    const int b = blockIdx.x, tid = threadIdx.x;
    const int T = lengths[b];
    const float* scores = out + BB + (size_t)b * NN;
    const float* logits = g_logits + (size_t)b * NN;

    const float sc0 = scores[tid],        sc1 = scores[tid + 1024];
    const float lg0 = logits[tid],        lg1 = logits[tid + 1024];
    const bool  v0  = tid < T,            v1  = (tid + 1024) < T;
    const float ml0 = v0 ? lg0 : NEGV,    ml1 = v1 ? lg1 : NEGV;

    const float mx  = block_max(fmaxf(ml0, ml1), s_red);
    const float e0  = expf(ml0 - mx), e1 = expf(ml1 - mx);
    const float2 dn = block_sum2(e0 + e1,
                                 (v0 ? e0 * sc0 : 0.0f) + (v1 ? e1 * sc1 : 0.0f),
                                 s_red);
    const float attn = dn.y / dn.x;

    // ---- radix-select k-th largest (exact, with tie handling) ----
    const uint32_t k0 = fkey(sc0, v0), k1 = fkey(sc1, v1);
    int kk = T / 10;
    if (kk < 1) kk = 1;
    uint32_t prefix = 0, rem = (uint32_t)kk;

    #pragma unroll 1
    for (int shift = 24; shift >= 0; shift -= 8) {
        if (tid < 256) s_hist[tid] = 0;
        __syncthreads();
        const uint32_t msk = (shift == 24) ? 0u : (0xFFFFFFFFu << (shift + 8));
        if ((k0 & msk) == prefix) atomicAdd(&s_hist[(k0 >> shift) & 255], 1u);
        if ((k1 & msk) == prefix) atomicAdd(&s_hist[(k1 >> shift) & 255], 1u);
        __syncthreads();
        if (tid < 32) {
            const int hi = 255 - tid * 8;
            uint32_t cnt[8], csum = 0;
            #pragma unroll
            for (int i = 0; i < 8; i++) { cnt[i] = s_hist[hi - i]; csum += cnt[i]; }
            uint32_t run = csum;
            #pragma unroll
            for (int o = 1; o < 32; o <<= 1) {
                uint32_t t = __shfl_up_sync(0xffffffffu, run, o);
                if (tid >= o) run += t;
            }
            const uint32_t excl = run - csum;
            if (excl < rem && rem <= excl + csum) {
                uint32_t r = rem - excl, c2 = 0;
                #pragma unroll
                for (int i = 0; i < 8; i++) {
                    if (c2 + cnt[i] >= r) { s_sel[0] = (uint32_t)(hi - i);
                                            s_sel[1] = r - c2; break; }
                    c2 += cnt[i];
                }
            }
        }
        __syncthreads();
        prefix |= s_sel[0] << shift;
        rem = s_sel[1];
        __syncthreads();
    }

    const uint32_t tkey = prefix;
    const float thr = (tkey & 0x80000000u)
                    ? __uint_as_float(tkey ^ 0x80000000u)
                    : __uint_as_float(~tkey);
    const float sg = (k0 > tkey ? sc0 : 0.0f) + (k1 > tkey ? sc1 : 0.0f);
    const float sum_gt = block_sum(sg, s_red);
    const float tsum = sum_gt + (float)rem * thr;

    if (tid == 0)
        out[b] = (T > 0) ? 0.5f * attn + 0.5f * (tsum / (float)kk) : 0.0f;
}

// ---------------------------------------------------------------------------
extern "C" void kernel_launch(void* const* d_in, const int* in_sizes, int n_in,
                              void* d_out, int out_size) {
    const float* x    = (const float*)d_in[0];
    const int*   lens = (const int*)  d_in[1];
    const float* W1   = (const float*)d_in[2];
    const float* b1   = (const float*)d_in[3];
    const float* ln_g = (const float*)d_in[4];
    const float* ln_b = (const float*)d_in[5];
    const float* Wa1  = (const float*)d_in[6];
    const float* ba1  = (const float*)d_in[7];
    const float* Wa2  = (const float*)d_in[8];
    const float* ba2  = (const float*)d_in[9];
    const float* Wc   = (const float*)d_in[10];
    const float* bc   = (const float*)d_in[11];
    float* out = (float*)d_out;

    // idempotent, executes immediately (not stream-captured)
    cudaFuncSetAttribute(gemm1_kernel,
                         cudaFuncAttributeMaxDynamicSharedMemorySize, SM1);
    cudaFuncSetAttribute(gemm2_kernel,
                         cudaFuncAttributeMaxDynamicSharedMemorySize, SM2);

    convert_weights_kernel<<<288, 256>>>(W1, Wa1);
    gemm1_kernel<<<MTOT / 64, 256, SM1>>>(x, b1, ln_g, ln_b, Wc, bc, out);
    gemm2_kernel<<<MTOT / 64, 256, SM2>>>(ba1, Wa2, ba2);
    finalize_kernel<<<BB, 1024>>>(lens, out);
}